// round 3
// baseline (speedup 1.0000x reference)
#include <cuda_runtime.h>
#include <cstdint>
#include <math.h>

#define BB 4
#define NN 2048
#define KK 48
#define HH 128
#define NODES (BB*NN)          // 8192
#define FFW 512
#define SCALE_INV (1.0f/30.0f)
#define LD 136                 // smem leading dim (floats); 136%32==8 -> conflict-free frags
#define LDW1C 264              // leading dim for 256-wide FF1 weight tile; 264%32==8

// -------- scratch (device globals; no allocation allowed) --------
__device__ float g_m1[(size_t)NODES * KK * HH];   // 201 MB  (post-gelu layer1 activations)
__device__ float g_h [(size_t)NODES * HH];        // 4 MB    (h after edge-message residual)
__device__ float g_t [(size_t)NODES * FFW];       // 16 MB   (post-gelu FFN hidden)

// -------- helpers --------
__device__ __forceinline__ uint32_t f2tf(float x) {
    uint32_t u;
    asm("cvt.rna.tf32.f32 %0, %1;" : "=r"(u) : "f"(x));
    return u;
}

__device__ __forceinline__ void mma8(float c[4],
                                     uint32_t a0, uint32_t a1, uint32_t a2, uint32_t a3,
                                     uint32_t b0, uint32_t b1) {
    asm volatile(
        "mma.sync.aligned.m16n8k8.row.col.f32.tf32.tf32.f32 "
        "{%0,%1,%2,%3},{%4,%5,%6,%7},{%8,%9},{%0,%1,%2,%3};"
        : "+f"(c[0]), "+f"(c[1]), "+f"(c[2]), "+f"(c[3])
        : "r"(a0), "r"(a1), "r"(a2), "r"(a3), "r"(b0), "r"(b1));
}

__device__ __forceinline__ float gelu_tanh(float x) {   // jax.nn.gelu approximate=True
    float x3 = x * x * x;
    return 0.5f * x * (1.0f + tanhf(0.7978845608028654f * (x + 0.044715f * x3)));
}
__device__ __forceinline__ float gelu_erf(float x) {    // jax.nn.gelu approximate=False
    return 0.5f * x * (1.0f + erff(x * 0.7071067811865476f));
}

// ============================================================================
// Kernel 1: layer1.  A = concat(h_nb, h_E) [2 nodes -> M=128 rows (48 real +16
// pad per node)], W1 (256x128) resident in smem.  A staged in two 128-k chunks.
// Writes m1 = gelu_tanh(A@W1 + b1) for real rows to g_m1.
// ============================================================================
__global__ __launch_bounds__(256, 1) void k_edge1(
    const float* __restrict__ hV, const float* __restrict__ hE,
    const int* __restrict__ Eidx, const float* __restrict__ W1,
    const float* __restrict__ b1)
{
    extern __shared__ uint32_t sm[];
    uint32_t* sW = sm;               // 256 x LD (tf32)
    uint32_t* sA = sm + 256 * LD;    // 128 x LD (tf32)

    const int tid  = threadIdx.x;
    const int lane = tid & 31, wid = tid >> 5;
    const int g = lane >> 2, tg = lane & 3;
    const int wm = wid >> 2, wn = wid & 3;   // warps: 2 (m64) x 4 (n32)

    // load W1 once (persistent CTA)
    for (int idx = tid; idx < 256 * 128; idx += 256) {
        int k = idx >> 7, n = idx & 127;
        sW[k * LD + n] = f2tf(W1[idx]);
    }
    __syncthreads();

    for (int p = blockIdx.x; p < NODES / 2; p += gridDim.x) {
        const int node0 = 2 * p;
        float acc[4][4][4];
        #pragma unroll
        for (int i = 0; i < 4; i++)
            #pragma unroll
            for (int j = 0; j < 4; j++)
                #pragma unroll
                for (int q = 0; q < 4; q++) acc[i][j][q] = 0.0f;

        // chunk 0: h_nb (gathered) with W1 rows [0,128); chunk 1: h_E with rows [128,256)
        for (int c = 0; c < 2; c++) {
            __syncthreads();
            for (int r = wid; r < 128; r += 8) {      // one warp per row
                const int er   = r & 63;
                const int node = node0 + (r >> 6);
                float4 v = make_float4(0.f, 0.f, 0.f, 0.f);
                if (er < KK) {
                    const float* src;
                    if (c == 0) {
                        int nb = Eidx[node * KK + er];
                        src = hV + ((size_t)((node >> 11) * NN + nb)) * HH;
                    } else {
                        src = hE + ((size_t)(node * KK + er)) * HH;
                    }
                    v = reinterpret_cast<const float4*>(src)[lane];
                }
                uint32_t* d = sA + r * LD + lane * 4;
                d[0] = f2tf(v.x); d[1] = f2tf(v.y); d[2] = f2tf(v.z); d[3] = f2tf(v.w);
            }
            __syncthreads();

            #pragma unroll 1
            for (int s = 0; s < 16; s++) {
                const int kk = s * 8;
                uint32_t a[4][4];
                #pragma unroll
                for (int i = 0; i < 4; i++) {
                    int r0 = wm * 64 + i * 16 + g;
                    a[i][0] = sA[r0 * LD + kk + tg];
                    a[i][1] = sA[(r0 + 8) * LD + kk + tg];
                    a[i][2] = sA[r0 * LD + kk + tg + 4];
                    a[i][3] = sA[(r0 + 8) * LD + kk + tg + 4];
                }
                const int kw = c * 128 + kk;
                #pragma unroll
                for (int j = 0; j < 4; j++) {
                    int n0 = wn * 32 + j * 8;
                    uint32_t b0 = sW[(kw + tg) * LD + n0 + g];
                    uint32_t b1r = sW[(kw + tg + 4) * LD + n0 + g];
                    #pragma unroll
                    for (int i = 0; i < 4; i++)
                        mma8(acc[i][j], a[i][0], a[i][1], a[i][2], a[i][3], b0, b1r);
                }
            }
        }

        // epilogue: bias + gelu + store real rows
        #pragma unroll
        for (int j = 0; j < 4; j++) {
            const int col = wn * 32 + j * 8 + 2 * tg;
            const float bb0 = b1[col], bb1 = b1[col + 1];
            #pragma unroll
            for (int i = 0; i < 4; i++) {
                const int r0 = wm * 64 + i * 16 + g;
                const int er0 = r0 & 63, er1 = (r0 + 8) & 63;
                const int nd = node0 + (r0 >> 6);
                float v0 = gelu_tanh(acc[i][j][0] + bb0);
                float v1 = gelu_tanh(acc[i][j][1] + bb1);
                float v2 = gelu_tanh(acc[i][j][2] + bb0);
                float v3 = gelu_tanh(acc[i][j][3] + bb1);
                if (er0 < KK) {
                    float2* d = (float2*)(g_m1 + ((size_t)(nd * KK + er0)) * HH + col);
                    *d = make_float2(v0, v1);
                }
                if (er1 < KK) {
                    float2* d = (float2*)(g_m1 + ((size_t)(nd * KK + er1)) * HH + col);
                    *d = make_float2(v2, v3);
                }
            }
        }
    }
}

// ============================================================================
// Kernel 2: layers 2+3 fused + mask_attend + reduce over K + /30 + residual.
// W2, W3 resident; m2 stays in smem.  Warp wm owns exactly one node -> the
// row-reduction is a pure in-warp shuffle reduce.  Writes g_h.
// ============================================================================
__global__ __launch_bounds__(256, 1) void k_edge2(
    const float* __restrict__ hV, const float* __restrict__ mask_att,
    const float* __restrict__ W2, const float* __restrict__ b2,
    const float* __restrict__ W3, const float* __restrict__ b3)
{
    extern __shared__ uint32_t sm[];
    uint32_t* sW2 = sm;                 // 128 x LD
    uint32_t* sW3 = sm + 128 * LD;      // 128 x LD
    uint32_t* sA  = sm + 256 * LD;      // 128 x LD
    float* sMask  = (float*)(sm + 384 * LD);  // 128

    const int tid  = threadIdx.x;
    const int lane = tid & 31, wid = tid >> 5;
    const int g = lane >> 2, tg = lane & 3;
    const int wm = wid >> 2, wn = wid & 3;

    for (int idx = tid; idx < 128 * 128; idx += 256) {
        int k = idx >> 7, n = idx & 127;
        sW2[k * LD + n] = f2tf(W2[idx]);
        sW3[k * LD + n] = f2tf(W3[idx]);
    }
    __syncthreads();

    for (int p = blockIdx.x; p < NODES / 2; p += gridDim.x) {
        const int node0 = 2 * p;

        __syncthreads();
        // stage m1 tile + mask
        for (int r = wid; r < 128; r += 8) {
            const int er = r & 63;
            const int node = node0 + (r >> 6);
            float4 v = make_float4(0.f, 0.f, 0.f, 0.f);
            if (er < KK)
                v = reinterpret_cast<const float4*>(g_m1 + ((size_t)(node * KK + er)) * HH)[lane];
            uint32_t* d = sA + r * LD + lane * 4;
            d[0] = f2tf(v.x); d[1] = f2tf(v.y); d[2] = f2tf(v.z); d[3] = f2tf(v.w);
        }
        for (int r = tid; r < 128; r += 256) {
            const int er = r & 63;
            const int node = node0 + (r >> 6);
            sMask[r] = (er < KK) ? mask_att[node * KK + er] : 0.0f;
        }
        __syncthreads();

        // ---- layer 2 ----
        float acc[4][4][4];
        #pragma unroll
        for (int i = 0; i < 4; i++)
            #pragma unroll
            for (int j = 0; j < 4; j++)
                #pragma unroll
                for (int q = 0; q < 4; q++) acc[i][j][q] = 0.0f;

        #pragma unroll 1
        for (int s = 0; s < 16; s++) {
            const int kk = s * 8;
            uint32_t a[4][4];
            #pragma unroll
            for (int i = 0; i < 4; i++) {
                int r0 = wm * 64 + i * 16 + g;
                a[i][0] = sA[r0 * LD + kk + tg];
                a[i][1] = sA[(r0 + 8) * LD + kk + tg];
                a[i][2] = sA[r0 * LD + kk + tg + 4];
                a[i][3] = sA[(r0 + 8) * LD + kk + tg + 4];
            }
            #pragma unroll
            for (int j = 0; j < 4; j++) {
                int n0 = wn * 32 + j * 8;
                uint32_t b0 = sW2[(kk + tg) * LD + n0 + g];
                uint32_t b1r = sW2[(kk + tg + 4) * LD + n0 + g];
                #pragma unroll
                for (int i = 0; i < 4; i++)
                    mma8(acc[i][j], a[i][0], a[i][1], a[i][2], a[i][3], b0, b1r);
            }
        }
        __syncthreads();
        // m2 = gelu(acc + b2) back into sA (tf32)
        #pragma unroll
        for (int j = 0; j < 4; j++) {
            const int col = wn * 32 + j * 8 + 2 * tg;
            const float bb0 = b2[col], bb1 = b2[col + 1];
            #pragma unroll
            for (int i = 0; i < 4; i++) {
                const int r0 = wm * 64 + i * 16 + g;
                sA[r0 * LD + col]           = f2tf(gelu_tanh(acc[i][j][0] + bb0));
                sA[r0 * LD + col + 1]       = f2tf(gelu_tanh(acc[i][j][1] + bb1));
                sA[(r0 + 8) * LD + col]     = f2tf(gelu_tanh(acc[i][j][2] + bb0));
                sA[(r0 + 8) * LD + col + 1] = f2tf(gelu_tanh(acc[i][j][3] + bb1));
            }
        }
        __syncthreads();

        // ---- layer 3 ----
        #pragma unroll
        for (int i = 0; i < 4; i++)
            #pragma unroll
            for (int j = 0; j < 4; j++)
                #pragma unroll
                for (int q = 0; q < 4; q++) acc[i][j][q] = 0.0f;

        #pragma unroll 1
        for (int s = 0; s < 16; s++) {
            const int kk = s * 8;
            uint32_t a[4][4];
            #pragma unroll
            for (int i = 0; i < 4; i++) {
                int r0 = wm * 64 + i * 16 + g;
                a[i][0] = sA[r0 * LD + kk + tg];
                a[i][1] = sA[(r0 + 8) * LD + kk + tg];
                a[i][2] = sA[r0 * LD + kk + tg + 4];
                a[i][3] = sA[(r0 + 8) * LD + kk + tg + 4];
            }
            #pragma unroll
            for (int j = 0; j < 4; j++) {
                int n0 = wn * 32 + j * 8;
                uint32_t b0 = sW3[(kk + tg) * LD + n0 + g];
                uint32_t b1r = sW3[(kk + tg + 4) * LD + n0 + g];
                #pragma unroll
                for (int i = 0; i < 4; i++)
                    mma8(acc[i][j], a[i][0], a[i][1], a[i][2], a[i][3], b0, b1r);
            }
        }

        // ---- mask + reduce over rows (warp wm == node node0+wm) ----
        const int node = node0 + wm;
        #pragma unroll
        for (int j = 0; j < 4; j++) {
            const int col = wn * 32 + j * 8 + 2 * tg;
            const float bb0 = b3[col], bb1 = b3[col + 1];
            float s0 = 0.f, s1 = 0.f;
            #pragma unroll
            for (int i = 0; i < 4; i++) {
                const int r0 = wm * 64 + i * 16 + g;
                const float m0 = sMask[r0], m8 = sMask[r0 + 8];
                s0 += m0 * (acc[i][j][0] + bb0) + m8 * (acc[i][j][2] + bb0);
                s1 += m0 * (acc[i][j][1] + bb1) + m8 * (acc[i][j][3] + bb1);
            }
            // reduce over the 8 g-lanes (lane bits 2..4)
            #pragma unroll
            for (int m = 4; m <= 16; m <<= 1) {
                s0 += __shfl_xor_sync(0xffffffffu, s0, m);
                s1 += __shfl_xor_sync(0xffffffffu, s1, m);
            }
            if (lane < 4) {   // g == 0
                const size_t base = (size_t)node * HH + col;
                g_h[base]     = hV[base]     + s0 * SCALE_INV;
                g_h[base + 1] = hV[base + 1] + s1 * SCALE_INV;
            }
        }
    }
}

// ============================================================================
// Kernel 3: FFN layer 1:  t = gelu_erf(h @ W_in + b_in).  CTA tile 64x256
// (blockIdx selects m-block and n-half), W_in half resident in smem.
// ============================================================================
__global__ __launch_bounds__(256, 1) void k_ff1(
    const float* __restrict__ Win, const float* __restrict__ bin)
{
    extern __shared__ uint32_t sm[];
    uint32_t* sW = sm;                  // 128 x LDW1C (n-width 256)
    uint32_t* sA = sm + 128 * LDW1C;    // 64 x LD

    const int tid  = threadIdx.x;
    const int lane = tid & 31, wid = tid >> 5;
    const int g = lane >> 2, tg = lane & 3;
    const int wm = wid >> 2, wn = wid & 3;   // 2 (m32) x 4 (n64)

    const int mblk = blockIdx.x >> 1;
    const int nh   = (blockIdx.x & 1) * 256;

    for (int idx = tid; idx < 128 * 256; idx += 256) {
        int k = idx >> 8, n = idx & 255;
        sW[k * LDW1C + n] = f2tf(Win[(size_t)k * FFW + nh + n]);
    }
    for (int idx = tid; idx < 64 * 32; idx += 256) {
        int r = idx >> 5, c4 = idx & 31;
        float4 v = reinterpret_cast<const float4*>(g_h + ((size_t)(mblk * 64 + r)) * HH)[c4];
        uint32_t* d = sA + r * LD + c4 * 4;
        d[0] = f2tf(v.x); d[1] = f2tf(v.y); d[2] = f2tf(v.z); d[3] = f2tf(v.w);
    }
    __syncthreads();

    float acc[2][8][4];
    #pragma unroll
    for (int i = 0; i < 2; i++)
        #pragma unroll
        for (int j = 0; j < 8; j++)
            #pragma unroll
            for (int q = 0; q < 4; q++) acc[i][j][q] = 0.0f;

    #pragma unroll 1
    for (int s = 0; s < 16; s++) {
        const int kk = s * 8;
        uint32_t a[2][4];
        #pragma unroll
        for (int i = 0; i < 2; i++) {
            int r0 = wm * 32 + i * 16 + g;
            a[i][0] = sA[r0 * LD + kk + tg];
            a[i][1] = sA[(r0 + 8) * LD + kk + tg];
            a[i][2] = sA[r0 * LD + kk + tg + 4];
            a[i][3] = sA[(r0 + 8) * LD + kk + tg + 4];
        }
        #pragma unroll
        for (int j = 0; j < 8; j++) {
            int n0 = wn * 64 + j * 8;
            uint32_t b0 = sW[(kk + tg) * LDW1C + n0 + g];
            uint32_t b1r = sW[(kk + tg + 4) * LDW1C + n0 + g];
            #pragma unroll
            for (int i = 0; i < 2; i++)
                mma8(acc[i][j], a[i][0], a[i][1], a[i][2], a[i][3], b0, b1r);
        }
    }

    #pragma unroll
    for (int j = 0; j < 8; j++) {
        const int col = wn * 64 + j * 8 + 2 * tg;
        const int nglob = nh + col;
        const float bb0 = bin[nglob], bb1 = bin[nglob + 1];
        #pragma unroll
        for (int i = 0; i < 2; i++) {
            const int row = mblk * 64 + wm * 32 + i * 16 + g;
            float2* d0 = (float2*)(g_t + (size_t)row * FFW + nglob);
            float2* d1 = (float2*)(g_t + (size_t)(row + 8) * FFW + nglob);
            *d0 = make_float2(gelu_erf(acc[i][j][0] + bb0), gelu_erf(acc[i][j][1] + bb1));
            *d1 = make_float2(gelu_erf(acc[i][j][2] + bb0), gelu_erf(acc[i][j][3] + bb1));
        }
    }
}

// ============================================================================
// Kernel 4: FFN layer 2 + residual + mask_V -> d_out.  K=512 staged in four
// 128-wide chunks.  CTA tile 64x128.
// ============================================================================
__global__ __launch_bounds__(256, 1) void k_ff2(
    const float* __restrict__ Wout, const float* __restrict__ bout,
    const float* __restrict__ maskV, float* __restrict__ out)
{
    extern __shared__ uint32_t sm[];
    uint32_t* sW = sm;               // 128 x LD
    uint32_t* sA = sm + 128 * LD;    // 64 x LD

    const int tid  = threadIdx.x;
    const int lane = tid & 31, wid = tid >> 5;
    const int g = lane >> 2, tg = lane & 3;
    const int wm = wid >> 2, wn = wid & 3;   // 2 (m32) x 4 (n32)
    const int mblk = blockIdx.x;

    float acc[2][4][4];
    #pragma unroll
    for (int i = 0; i < 2; i++)
        #pragma unroll
        for (int j = 0; j < 4; j++)
            #pragma unroll
            for (int q = 0; q < 4; q++) acc[i][j][q] = 0.0f;

    for (int kc = 0; kc < 4; kc++) {
        __syncthreads();
        for (int idx = tid; idx < 128 * 128; idx += 256) {
            int k = idx >> 7, n = idx & 127;
            sW[k * LD + n] = f2tf(Wout[(size_t)(kc * 128 + k) * HH + n]);
        }
        for (int idx = tid; idx < 64 * 32; idx += 256) {
            int r = idx >> 5, c4 = idx & 31;
            float4 v = reinterpret_cast<const float4*>(
                g_t + ((size_t)(mblk * 64 + r)) * FFW + kc * 128)[c4];
            uint32_t* d = sA + r * LD + c4 * 4;
            d[0] = f2tf(v.x); d[1] = f2tf(v.y); d[2] = f2tf(v.z); d[3] = f2tf(v.w);
        }
        __syncthreads();

        #pragma unroll 1
        for (int s = 0; s < 16; s++) {
            const int kk = s * 8;
            uint32_t a[2][4];
            #pragma unroll
            for (int i = 0; i < 2; i++) {
                int r0 = wm * 32 + i * 16 + g;
                a[i][0] = sA[r0 * LD + kk + tg];
                a[i][1] = sA[(r0 + 8) * LD + kk + tg];
                a[i][2] = sA[r0 * LD + kk + tg + 4];
                a[i][3] = sA[(r0 + 8) * LD + kk + tg + 4];
            }
            #pragma unroll
            for (int j = 0; j < 4; j++) {
                int n0 = wn * 32 + j * 8;
                uint32_t b0 = sW[(kk + tg) * LD + n0 + g];
                uint32_t b1r = sW[(kk + tg + 4) * LD + n0 + g];
                #pragma unroll
                for (int i = 0; i < 2; i++)
                    mma8(acc[i][j], a[i][0], a[i][1], a[i][2], a[i][3], b0, b1r);
            }
        }
    }

    #pragma unroll
    for (int j = 0; j < 4; j++) {
        const int col = wn * 32 + j * 8 + 2 * tg;
        const float bb0 = bout[col], bb1 = bout[col + 1];
        #pragma unroll
        for (int i = 0; i < 2; i++) {
            const int row0 = mblk * 64 + wm * 32 + i * 16 + g;
            #pragma unroll
            for (int h = 0; h < 2; h++) {
                const int row = row0 + h * 8;
                const float mv = maskV[row];
                const size_t base = (size_t)row * HH + col;
                float v0 = acc[i][j][h * 2 + 0] + bb0 + g_h[base];
                float v1 = acc[i][j][h * 2 + 1] + bb1 + g_h[base + 1];
                float2* d = (float2*)(out + base);
                *d = make_float2(mv * v0, mv * v1);
            }
        }
    }
}

// ============================================================================
extern "C" void kernel_launch(void* const* d_in, const int* in_sizes, int n_in,
                              void* d_out, int out_size)
{
    const float* hV    = (const float*)d_in[0];
    const float* hE    = (const float*)d_in[1];
    const int*   Eidx  = (const int*)  d_in[2];
    const float* maskV = (const float*)d_in[3];
    const float* maskA = (const float*)d_in[4];
    const float* W1    = (const float*)d_in[5];
    const float* b1    = (const float*)d_in[6];
    const float* W2    = (const float*)d_in[7];
    const float* b2    = (const float*)d_in[8];
    const float* W3    = (const float*)d_in[9];
    const float* b3    = (const float*)d_in[10];
    const float* Win   = (const float*)d_in[11];
    const float* bin   = (const float*)d_in[12];
    const float* Wout  = (const float*)d_in[13];
    const float* bout  = (const float*)d_in[14];
    float* out = (float*)d_out;

    const int smA1 = (256 * LD + 128 * LD) * 4;            // 208,896
    const int smA2 = (384 * LD) * 4 + 128 * 4;             // 209,408
    const int smC1 = (128 * LDW1C + 64 * LD) * 4;          // 169,984
    const int smC2 = (128 * LD + 64 * LD) * 4;             // 104,448

    cudaFuncSetAttribute(k_edge1, cudaFuncAttributeMaxDynamicSharedMemorySize, smA1);
    cudaFuncSetAttribute(k_edge2, cudaFuncAttributeMaxDynamicSharedMemorySize, smA2);
    cudaFuncSetAttribute(k_ff1,   cudaFuncAttributeMaxDynamicSharedMemorySize, smC1);
    cudaFuncSetAttribute(k_ff2,   cudaFuncAttributeMaxDynamicSharedMemorySize, smC2);

    k_edge1<<<152, 256, smA1>>>(hV, hE, Eidx, W1, b1);
    k_edge2<<<152, 256, smA2>>>(hV, maskA, W2, b2, W3, b3);
    k_ff1  <<<256, 256, smC1>>>(Win, bin);
    k_ff2  <<<128, 256, smC2>>>(Wout, bout, maskV, out);
}